// round 2
// baseline (speedup 1.0000x reference)
#include <cuda_runtime.h>
#include <math.h>

#define NUM_NEURONS 2048
#define D_MODEL     1024
#define BATCH       64
#define NCHUNK      4
#define NEUR_PER_CHUNK (NUM_NEURONS / NCHUNK)    // 512
#define DCHUNK      128
#define KSPLIT      32                           // total partial buffers (8 per chunk)

// Scratch (static device globals — no runtime allocation)
__device__ __align__(16) float g_xT[D_MODEL * BATCH];             // x transposed [d][b]
__device__ __align__(16) float g_S[2 * NUM_NEURONS * BATCH];      // sums, [k][b] (cos rows then sin rows)
__device__ __align__(16) float g_part[KSPLIT * BATCH * D_MODEL];  // GEMM partials

// ---------------------------------------------------------------------------
// Transpose x -> [d][b] so main-kernel shared stage is coalesced.
// ---------------------------------------------------------------------------
__global__ void prep_x(const float* __restrict__ x) {
    int i = blockIdx.x * 256 + threadIdx.x;   // 65536 total
    g_xT[(i & 1023) * BATCH + (i >> 10)] = x[i];
}

// ---------------------------------------------------------------------------
// Main: per CTA, 2 neurons x all 64 batches; d-loop staged through shared.
// 1/(1+|W|) computed at stage time (MUFU.RCP, amortized 64x). MUFU-bound.
// ---------------------------------------------------------------------------
__global__ __launch_bounds__(128) void resonant_main(const float* __restrict__ t,
                                                     const float* __restrict__ W,
                                                     const float* __restrict__ Bp,
                                                     int chunk) {
    __shared__ float  x_sh[DCHUNK][BATCH];   // 32 KB, lane=b conflict-free
    __shared__ float2 rB_sh[2][DCHUNK];      // 2 KB, warp-broadcast reads

    int tid = threadIdx.x;
    int b   = tid & 63;
    int nl  = tid >> 6;
    int n0  = (chunk * (NEUR_PER_CHUNK / 2) + blockIdx.x) * 2;

    float tb = t[b];
    float cs = 0.0f, sn = 0.0f;

    for (int d0 = 0; d0 < D_MODEL; d0 += DCHUNK) {
        float4*       xs4 = reinterpret_cast<float4*>(&x_sh[0][0]);
        const float4* xg4 = reinterpret_cast<const float4*>(g_xT + d0 * BATCH);
        #pragma unroll
        for (int i = 0; i < (DCHUNK * BATCH / 4) / 128; i++)
            xs4[tid + i * 128] = xg4[tid + i * 128];
        {
            float w0 = W [(n0 + 0) * D_MODEL + d0 + tid];
            float p0 = Bp[(n0 + 0) * D_MODEL + d0 + tid];
            rB_sh[0][tid] = make_float2(__fdividef(1.0f, 1.0f + fabsf(w0)), p0);
            float w1 = W [(n0 + 1) * D_MODEL + d0 + tid];
            float p1 = Bp[(n0 + 1) * D_MODEL + d0 + tid];
            rB_sh[1][tid] = make_float2(__fdividef(1.0f, 1.0f + fabsf(w1)), p1);
        }
        __syncthreads();

        #pragma unroll 8
        for (int dd = 0; dd < DCHUNK; dd++) {
            float2 rb = rB_sh[nl][dd];
            float th  = fmaf(x_sh[dd][b], rb.x, rb.y) + tb;
            float s, c;
            __sincosf(th, &s, &c);
            cs += c;
            sn += s;
        }
        __syncthreads();
    }

    int n = n0 + nl;
    g_S[n * BATCH + b]                 = cs;  // cos row: k = n
    g_S[(n + NUM_NEURONS) * BATCH + b] = sn;  // sin row: k = n + 2048
}

// ---------------------------------------------------------------------------
// GEMM chunk: processes K rows for one neuron chunk (512 cos + 512 sin rows),
// split 8 ways by K. 64x64 output tile, 4x4 register tile, LDS.128 loads.
// Partial index = chunk*8 + ksub -> disjoint, deterministic, no atomics.
// ---------------------------------------------------------------------------
__global__ __launch_bounds__(256) void gemm_kernel(const float* __restrict__ Pr,
                                                   const float* __restrict__ Pi,
                                                   int chunk) {
    __shared__ float S_sh[32][64];
    __shared__ float P_sh[32][68];   // 68 floats/row: 16B-aligned rows + conflict relief

    int tid  = threadIdx.x;
    int tx   = tid & 15;   // j groups of 4
    int ty   = tid >> 4;   // b groups of 4
    int j0   = blockIdx.x * 64;
    int ksub = blockIdx.y; // 0..7 (0-3 cos region, 4-7 sin region)

    const float* P;
    int k0, kbase;
    if (ksub < 4) {
        P = Pr; kbase = chunk * 512 + ksub * 128;       k0 = kbase;
    } else {
        P = Pi; kbase = chunk * 512 + (ksub - 4) * 128; k0 = NUM_NEURONS + kbase;
    }

    float acc[4][4] = {};

    for (int kc = 0; kc < 128; kc += 32) {
        // stage S tile: 32x64, coalesced (b contiguous)
        #pragma unroll
        for (int i = 0; i < 8; i++) {
            int lin = tid + i * 256;
            S_sh[lin >> 6][lin & 63] = g_S[(k0 + kc) * BATCH + lin];
        }
        // stage P tile transposed: float4 global reads, scalar smem stores
        {
            int jl  = tid >> 2;
            int kk0 = (tid & 3) * 8;
            const float4* src = reinterpret_cast<const float4*>(
                P + (j0 + jl) * NUM_NEURONS + kbase + kc + kk0);
            float4 v0 = src[0], v1 = src[1];
            P_sh[kk0 + 0][jl] = v0.x; P_sh[kk0 + 1][jl] = v0.y;
            P_sh[kk0 + 2][jl] = v0.z; P_sh[kk0 + 3][jl] = v0.w;
            P_sh[kk0 + 4][jl] = v1.x; P_sh[kk0 + 5][jl] = v1.y;
            P_sh[kk0 + 6][jl] = v1.z; P_sh[kk0 + 7][jl] = v1.w;
        }
        __syncthreads();

        #pragma unroll
        for (int kk = 0; kk < 32; kk++) {
            float4 a = *reinterpret_cast<const float4*>(&S_sh[kk][ty * 4]);
            float4 p = *reinterpret_cast<const float4*>(&P_sh[kk][tx * 4]);
            float av[4] = {a.x, a.y, a.z, a.w};
            float pv[4] = {p.x, p.y, p.z, p.w};
            #pragma unroll
            for (int ii = 0; ii < 4; ii++)
                #pragma unroll
                for (int jj = 0; jj < 4; jj++)
                    acc[ii][jj] = fmaf(av[ii], pv[jj], acc[ii][jj]);
        }
        __syncthreads();
    }

    float* dst = g_part + (chunk * 8 + ksub) * (BATCH * D_MODEL);
    #pragma unroll
    for (int ii = 0; ii < 4; ii++) {
        float4 v = make_float4(acc[ii][0], acc[ii][1], acc[ii][2], acc[ii][3]);
        *reinterpret_cast<float4*>(dst + (ty * 4 + ii) * D_MODEL + j0 + tx * 4) = v;
    }
}

// ---------------------------------------------------------------------------
// Epilogue: reduce K-split partials + SiLU.
// ---------------------------------------------------------------------------
__global__ __launch_bounds__(256) void epilogue(float* __restrict__ out) {
    int i = blockIdx.x * 256 + threadIdx.x;   // 65536 outputs
    float s = 0.0f;
    #pragma unroll
    for (int ks = 0; ks < KSPLIT; ks++)
        s += g_part[ks * (BATCH * D_MODEL) + i];
    out[i] = s / (1.0f + expf(-s));           // silu
}

// ---------------------------------------------------------------------------
// Launch: pipeline main-chunks (MUFU pipe) with gemm-chunks (FMA pipe) via
// stream fork/join — fully graph-capturable (event record/wait only).
// Inputs: x, t, W, B_p, proj_real_w, proj_imag_w, sin_table, cos_table.
// Tables unused: exact HW sincos is ~1e-6 from the LUT-lerp reference.
// ---------------------------------------------------------------------------
extern "C" void kernel_launch(void* const* d_in, const int* in_sizes, int n_in,
                              void* d_out, int out_size) {
    const float* x  = (const float*)d_in[0];
    const float* t  = (const float*)d_in[1];
    const float* W  = (const float*)d_in[2];
    const float* Bp = (const float*)d_in[3];
    const float* Pr = (const float*)d_in[4];
    const float* Pi = (const float*)d_in[5];
    float* out = (float*)d_out;

    static cudaStream_t s1 = nullptr;
    static cudaEvent_t  evm[NCHUNK];
    static cudaEvent_t  evj;
    if (!s1) {
        cudaStreamCreateWithFlags(&s1, cudaStreamNonBlocking);
        for (int i = 0; i < NCHUNK; i++)
            cudaEventCreateWithFlags(&evm[i], cudaEventDisableTiming);
        cudaEventCreateWithFlags(&evj, cudaEventDisableTiming);
    }

    prep_x<<<(BATCH * D_MODEL + 255) / 256, 256>>>(x);

    dim3 gg(D_MODEL / 64, 8);
    for (int c = 0; c < NCHUNK; c++) {
        resonant_main<<<NEUR_PER_CHUNK / 2, 128>>>(t, W, Bp, c);
        cudaEventRecord(evm[c], 0);
        cudaStreamWaitEvent(s1, evm[c], 0);
        gemm_kernel<<<gg, 256, 0, s1>>>(Pr, Pi, c);
    }
    cudaEventRecord(evj, s1);
    cudaStreamWaitEvent(0, evj, 0);

    epilogue<<<(BATCH * D_MODEL + 255) / 256, 256>>>(out);
}

// round 3
// speedup vs baseline: 2.6528x; 2.6528x over previous
#include <cuda_runtime.h>
#include <math.h>

#define NUM_NEURONS 2048
#define D_MODEL     1024
#define BATCH       64
#define KSPLIT      32
#define KCHUNK      128          // K rows per GEMM CTA
#define DCHUNK      128

// Scratch (static device globals — no runtime allocation)
__device__ __align__(16) float g_xT[D_MODEL * BATCH];             // x transposed [d][b]
__device__ __align__(16) float g_S[2 * NUM_NEURONS * BATCH];      // sums [k][b]: cos rows then sin rows
__device__ __align__(16) float g_part[KSPLIT * BATCH * D_MODEL];  // GEMM partials

// ---------------------------------------------------------------------------
// Transpose x -> [d][b] so main-kernel shared stage is coalesced.
// ---------------------------------------------------------------------------
__global__ void prep_x(const float* __restrict__ x) {
    int i = blockIdx.x * 256 + threadIdx.x;   // 65536 total
    g_xT[(i & 1023) * BATCH + (i >> 10)] = x[i];
}

// ---------------------------------------------------------------------------
// FMA-pipe sincos: quadrant reduction via magic-number round; Taylor deg7/deg6
// on phi in [-pi/4, pi/4]. Abs err <= ~4e-6. Runs entirely on fma/alu pipes,
// in parallel with MUFU-path elements.
// ---------------------------------------------------------------------------
__device__ __forceinline__ void sincos_poly(float th, float& s_out, float& c_out) {
    const float TWO_OVER_PI = 0.636619772f;
    const float MAGIC = 12582912.0f;       // 1.5 * 2^23
    float w   = th * TWO_OVER_PI;          // quarter-turns
    float big = w + MAGIC;                 // round-to-nearest-even
    int   qi  = __float_as_int(big);       // mantissa low bits = q mod 4
    float r   = big - MAGIC;
    float u   = w - r;                     // [-0.5, 0.5]
    float u2  = u * u;
    float sp  = fmaf(u2, fmaf(u2, fmaf(u2, -4.6817541e-3f, 7.9692626e-2f),
                              -6.4596410e-1f), 1.57079633f) * u;   // sin(u*pi/2)
    float cp  = fmaf(u2, fmaf(u2, fmaf(u2, -2.0864648e-2f, 2.5369510e-1f),
                              -1.2337006f), 1.0f);                 // cos(u*pi/2)
    float ss = (qi & 1) ? cp : sp;
    float cc = (qi & 1) ? sp : cp;
    if (qi & 2)       ss = -ss;
    if ((qi + 1) & 2) cc = -cc;
    s_out = ss; c_out = cc;
}

// ---------------------------------------------------------------------------
// Main: per CTA, 2 neurons x all 64 batches; d-loop staged through shared.
// Dual-path sincos: 3/4 MUFU, 1/4 FMA-pipe polynomial (pipe balance).
// ---------------------------------------------------------------------------
__global__ __launch_bounds__(128) void resonant_main(const float* __restrict__ t,
                                                     const float* __restrict__ W,
                                                     const float* __restrict__ Bp) {
    __shared__ float  x_sh[DCHUNK][BATCH];   // 32 KB, lane=b conflict-free
    __shared__ float2 rB_sh[2][DCHUNK];      // 2 KB, warp-broadcast reads

    int tid = threadIdx.x;
    int b   = tid & 63;
    int nl  = tid >> 6;
    int n0  = blockIdx.x * 2;

    float tb = t[b];
    float cs = 0.0f, sn = 0.0f;

    for (int d0 = 0; d0 < D_MODEL; d0 += DCHUNK) {
        float4*       xs4 = reinterpret_cast<float4*>(&x_sh[0][0]);
        const float4* xg4 = reinterpret_cast<const float4*>(g_xT + d0 * BATCH);
        #pragma unroll
        for (int i = 0; i < (DCHUNK * BATCH / 4) / 128; i++)
            xs4[tid + i * 128] = xg4[tid + i * 128];
        {
            float w0 = W [(n0 + 0) * D_MODEL + d0 + tid];
            float p0 = Bp[(n0 + 0) * D_MODEL + d0 + tid];
            rB_sh[0][tid] = make_float2(__fdividef(1.0f, 1.0f + fabsf(w0)), p0);
            float w1 = W [(n0 + 1) * D_MODEL + d0 + tid];
            float p1 = Bp[(n0 + 1) * D_MODEL + d0 + tid];
            rB_sh[1][tid] = make_float2(__fdividef(1.0f, 1.0f + fabsf(w1)), p1);
        }
        __syncthreads();

        #pragma unroll
        for (int dd = 0; dd < DCHUNK; dd += 4) {
            // 3 MUFU-path elements
            #pragma unroll
            for (int j = 0; j < 3; j++) {
                float2 rb = rB_sh[nl][dd + j];
                float th  = fmaf(x_sh[dd + j][b], rb.x, rb.y) + tb;
                float s, c;
                __sincosf(th, &s, &c);
                cs += c; sn += s;
            }
            // 1 FMA-pipe polynomial element
            {
                float2 rb = rB_sh[nl][dd + 3];
                float th  = fmaf(x_sh[dd + 3][b], rb.x, rb.y) + tb;
                float s, c;
                sincos_poly(th, s, c);
                cs += c; sn += s;
            }
        }
        __syncthreads();
    }

    int n = n0 + nl;
    g_S[n * BATCH + b]                 = cs;  // cos row: k = n
    g_S[(n + NUM_NEURONS) * BATCH + b] = sn;  // sin row: k = n + 2048
}

// ---------------------------------------------------------------------------
// GEMM: C[b][j] = sum_k S[k][b] * Pcat[j][k], K=4096 split 32 ways.
// 64x64 tile, 4x4 register tile, register double-buffered global staging.
// Partials disjoint per (jt, ks) -> deterministic, no atomics.
// ---------------------------------------------------------------------------
__global__ __launch_bounds__(256) void gemm_kernel(const float* __restrict__ Pr,
                                                   const float* __restrict__ Pi) {
    __shared__ float S_sh[32][64];
    __shared__ float P_sh[32][68];   // padded rows, 16B-aligned

    int tid = threadIdx.x;
    int tx  = tid & 15;   // j groups of 4
    int ty  = tid >> 4;   // b groups of 4
    int j0  = blockIdx.x * 64;
    int k0  = blockIdx.y * KCHUNK;

    const float* P     = (k0 < NUM_NEURONS) ? Pr : Pi;
    int          kbase = (k0 < NUM_NEURONS) ? k0 : k0 - NUM_NEURONS;

    // staging ownership
    int s_lin = tid;                       // 2 float4 per thread for S
    int jl    = tid >> 2;                  // P: one j row, 8 contiguous k
    int kk0   = (tid & 3) * 8;

    float4 sA, sB, pA, pB;
    {   // preload chunk 0
        const float4* sg = reinterpret_cast<const float4*>(g_S + k0 * BATCH);
        sA = sg[s_lin]; sB = sg[s_lin + 256];
        const float4* pg = reinterpret_cast<const float4*>(
            P + (j0 + jl) * NUM_NEURONS + kbase + kk0);
        pA = pg[0]; pB = pg[1];
    }

    float acc[4][4] = {};

    #pragma unroll
    for (int kc = 0; kc < KCHUNK; kc += 32) {
        __syncthreads();
        // commit staged regs to smem
        reinterpret_cast<float4*>(&S_sh[0][0])[s_lin]       = sA;
        reinterpret_cast<float4*>(&S_sh[0][0])[s_lin + 256] = sB;
        P_sh[kk0 + 0][jl] = pA.x; P_sh[kk0 + 1][jl] = pA.y;
        P_sh[kk0 + 2][jl] = pA.z; P_sh[kk0 + 3][jl] = pA.w;
        P_sh[kk0 + 4][jl] = pB.x; P_sh[kk0 + 5][jl] = pB.y;
        P_sh[kk0 + 6][jl] = pB.z; P_sh[kk0 + 7][jl] = pB.w;
        __syncthreads();

        // prefetch next chunk while computing this one
        if (kc + 32 < KCHUNK) {
            const float4* sg = reinterpret_cast<const float4*>(g_S + (k0 + kc + 32) * BATCH);
            sA = sg[s_lin]; sB = sg[s_lin + 256];
            const float4* pg = reinterpret_cast<const float4*>(
                P + (j0 + jl) * NUM_NEURONS + kbase + kc + 32 + kk0);
            pA = pg[0]; pB = pg[1];
        }

        #pragma unroll
        for (int kk = 0; kk < 32; kk++) {
            float4 a = *reinterpret_cast<const float4*>(&S_sh[kk][ty * 4]);
            float4 p = *reinterpret_cast<const float4*>(&P_sh[kk][tx * 4]);
            float av[4] = {a.x, a.y, a.z, a.w};
            float pv[4] = {p.x, p.y, p.z, p.w};
            #pragma unroll
            for (int ii = 0; ii < 4; ii++)
                #pragma unroll
                for (int jj = 0; jj < 4; jj++)
                    acc[ii][jj] = fmaf(av[ii], pv[jj], acc[ii][jj]);
        }
    }

    float* dst = g_part + blockIdx.y * (BATCH * D_MODEL);
    #pragma unroll
    for (int ii = 0; ii < 4; ii++) {
        float4 v = make_float4(acc[ii][0], acc[ii][1], acc[ii][2], acc[ii][3]);
        *reinterpret_cast<float4*>(dst + (ty * 4 + ii) * D_MODEL + j0 + tx * 4) = v;
    }
}

// ---------------------------------------------------------------------------
// Epilogue: reduce K-split partials + SiLU.
// ---------------------------------------------------------------------------
__global__ __launch_bounds__(256) void epilogue(float* __restrict__ out) {
    int i = blockIdx.x * 256 + threadIdx.x;   // 65536 outputs
    float s = 0.0f;
    #pragma unroll
    for (int ks = 0; ks < KSPLIT; ks++)
        s += g_part[ks * (BATCH * D_MODEL) + i];
    out[i] = s / (1.0f + expf(-s));           // silu
}

// ---------------------------------------------------------------------------
// Inputs: x, t, W, B_p, proj_real_w, proj_imag_w, sin_table, cos_table.
// Tables unused: HW sincos / poly are within ~4e-6 of the LUT-lerp reference.
// Single stream — chunked multi-stream overlap regressed (R2: small grids
// destroy occupancy on 148 SMs).
// ---------------------------------------------------------------------------
extern "C" void kernel_launch(void* const* d_in, const int* in_sizes, int n_in,
                              void* d_out, int out_size) {
    const float* x  = (const float*)d_in[0];
    const float* t  = (const float*)d_in[1];
    const float* W  = (const float*)d_in[2];
    const float* Bp = (const float*)d_in[3];
    const float* Pr = (const float*)d_in[4];
    const float* Pi = (const float*)d_in[5];
    float* out = (float*)d_out;

    prep_x<<<(BATCH * D_MODEL + 255) / 256, 256>>>(x);
    resonant_main<<<NUM_NEURONS / 2, 128>>>(t, W, Bp);
    dim3 gg(D_MODEL / 64, KSPLIT);
    gemm_kernel<<<gg, 256>>>(Pr, Pi);
    epilogue<<<(BATCH * D_MODEL + 255) / 256, 256>>>(out);
}